// round 1
// baseline (speedup 1.0000x reference)
#include <cuda_runtime.h>
#include <math.h>

#define B_ 4
#define L_ 4096
#define E_ 1024
#define H_ 16
#define D_ 64
#define C_ 64
#define NC_ (L_/C_)     // 64 chunks
#define BH_ (B_*H_)     // 64
#define M_ (B_*L_)      // 16384

// Scratch (device globals; allocation-free per harness rules)
__device__ float g_pq[(size_t)BH_*L_*D_];
__device__ float g_pk[(size_t)BH_*L_*D_];
__device__ float g_v [(size_t)BH_*L_*D_];
__device__ float g_Sl[(size_t)BH_*NC_*D_*D_];
__device__ float g_Sp[(size_t)BH_*NC_*D_*D_];
__device__ float g_zl[(size_t)BH_*NC_*D_];
__device__ float g_zp[(size_t)BH_*NC_*D_];
__device__ float g_at[(size_t)M_*E_];

// ---------------------------------------------------------------------------
// NT SGEMM: C[m][n] = sum_k A[m][k] * Bm[n][k]   (both row-major, K inner)
// MODE 0: identity epilogue -> [B,H,L,D] layout
// MODE 1: elu(x)+1 epilogue -> [B,H,L,D] layout
// MODE 2: +bias epilogue    -> plain row-major [M,N]
// ---------------------------------------------------------------------------
template<int MODE>
__global__ __launch_bounds__(256)
void gemm_nt(const float* __restrict__ A, const float* __restrict__ Bm,
             const float* __restrict__ bias, float* __restrict__ C,
             int M, int N, int K)
{
    const int BK = 16;
    __shared__ float As[BK][128];
    __shared__ float Bs[BK][128];
    int tid = threadIdx.x;
    int m0 = blockIdx.y * 128, n0 = blockIdx.x * 128;
    int ty = tid >> 4, tx = tid & 15;

    float acc[8][8];
#pragma unroll
    for (int i = 0; i < 8; i++)
#pragma unroll
        for (int j = 0; j < 8; j++) acc[i][j] = 0.f;

    for (int k0 = 0; k0 < K; k0 += BK) {
#pragma unroll
        for (int u = 0; u < 2; u++) {
            int f = tid + u * 256;          // float4 index in [0,512)
            int row = f >> 2;
            int kv = (f & 3) << 2;
            float4 a4 = *reinterpret_cast<const float4*>(A + (size_t)(m0 + row) * K + k0 + kv);
            As[kv + 0][row] = a4.x; As[kv + 1][row] = a4.y;
            As[kv + 2][row] = a4.z; As[kv + 3][row] = a4.w;
            float4 b4 = *reinterpret_cast<const float4*>(Bm + (size_t)(n0 + row) * K + k0 + kv);
            Bs[kv + 0][row] = b4.x; Bs[kv + 1][row] = b4.y;
            Bs[kv + 2][row] = b4.z; Bs[kv + 3][row] = b4.w;
        }
        __syncthreads();
#pragma unroll
        for (int kk = 0; kk < BK; kk++) {
            float a[8], b[8];
            *reinterpret_cast<float4*>(&a[0]) = *reinterpret_cast<const float4*>(&As[kk][ty * 8]);
            *reinterpret_cast<float4*>(&a[4]) = *reinterpret_cast<const float4*>(&As[kk][ty * 8 + 4]);
            *reinterpret_cast<float4*>(&b[0]) = *reinterpret_cast<const float4*>(&Bs[kk][tx * 8]);
            *reinterpret_cast<float4*>(&b[4]) = *reinterpret_cast<const float4*>(&Bs[kk][tx * 8 + 4]);
#pragma unroll
            for (int i = 0; i < 8; i++)
#pragma unroll
                for (int j = 0; j < 8; j++) acc[i][j] += a[i] * b[j];
        }
        __syncthreads();
    }

#pragma unroll
    for (int i = 0; i < 8; i++) {
        int row = m0 + ty * 8 + i;          // = b*L + l
#pragma unroll
        for (int j = 0; j < 8; j++) {
            int col = n0 + tx * 8 + j;      // = h*D + d (modes 0/1)
            float v = acc[i][j];
            if (MODE == 1) v = (v > 0.f) ? (v + 1.f) : expf(v);
            if (MODE == 2) {
                v += bias[col];
                C[(size_t)row * N + col] = v;
            } else {
                int b = row >> 12, l = row & (L_ - 1);
                int h = col >> 6,  d = col & (D_ - 1);
                C[(((size_t)(b * H_ + h)) * L_ + l) * D_ + d] = v;
            }
        }
    }
}

// ---------------------------------------------------------------------------
// Per-chunk local state: Sl = phi_k^T @ v  (D x D), zl = colsum(phi_k)
// ---------------------------------------------------------------------------
__global__ __launch_bounds__(256)
void chunk_state_kernel()
{
    int chunk = blockIdx.x, bh = blockIdx.y;
    __shared__ float pk_s[C_ * D_];
    __shared__ float v_s [C_ * D_];
    int tid = threadIdx.x;
    size_t rb = ((size_t)bh * L_ + (size_t)chunk * C_) * D_;
    const float4* pk4 = reinterpret_cast<const float4*>(g_pk + rb);
    const float4* v4  = reinterpret_cast<const float4*>(g_v  + rb);
#pragma unroll
    for (int u = 0; u < 4; u++) {
        int f = tid + u * 256;
        reinterpret_cast<float4*>(pk_s)[f] = pk4[f];
        reinterpret_cast<float4*>(v_s)[f]  = v4[f];
    }
    __syncthreads();

    int ty = tid >> 4, tx = tid & 15;
    float s[4][4]; float z[4];
#pragma unroll
    for (int i = 0; i < 4; i++) { z[i] = 0.f;
#pragma unroll
        for (int j = 0; j < 4; j++) s[i][j] = 0.f; }

    for (int r = 0; r < C_; r++) {
        float a[4], b[4];
#pragma unroll
        for (int i = 0; i < 4; i++) a[i] = pk_s[r * D_ + ty * 4 + i];
#pragma unroll
        for (int j = 0; j < 4; j++) b[j] = v_s[r * D_ + tx * 4 + j];
#pragma unroll
        for (int i = 0; i < 4; i++) {
            z[i] += a[i];
#pragma unroll
            for (int j = 0; j < 4; j++) s[i][j] += a[i] * b[j];
        }
    }
    size_t so = ((size_t)bh * NC_ + chunk) * D_ * D_;
#pragma unroll
    for (int i = 0; i < 4; i++)
#pragma unroll
        for (int j = 0; j < 4; j++)
            g_Sl[so + (ty * 4 + i) * D_ + tx * 4 + j] = s[i][j];
    if (tx == 0) {
        size_t zo = ((size_t)bh * NC_ + chunk) * D_;
#pragma unroll
        for (int i = 0; i < 4; i++) g_zl[zo + ty * 4 + i] = z[i];
    }
}

// ---------------------------------------------------------------------------
// Exclusive prefix over chunks (per bh): Sp[c] = sum_{c'<c} Sl[c'], same for z
// ---------------------------------------------------------------------------
__global__ __launch_bounds__(256)
void prefix_kernel()
{
    int bh = blockIdx.x;
    int tid = threadIdx.x;
    float acc[16];
#pragma unroll
    for (int j = 0; j < 16; j++) acc[j] = 0.f;
    for (int c = 0; c < NC_; c++) {
        size_t base = ((size_t)bh * NC_ + c) * D_ * D_;
#pragma unroll
        for (int j = 0; j < 16; j++) {
            int e = tid + j * 256;
            g_Sp[base + e] = acc[j];
            acc[j] += g_Sl[base + e];
        }
    }
    if (tid < D_) {
        float za = 0.f;
        for (int c = 0; c < NC_; c++) {
            size_t zb = ((size_t)bh * NC_ + c) * D_;
            g_zp[zb + tid] = za;
            za += g_zl[zb + tid];
        }
    }
}

// ---------------------------------------------------------------------------
// Fused intra+inter chunk attention.
//   A = tril(pq @ pk^T)  (inclusive)
//   num = A @ v + pq @ Sp;  den = rowsum(A) + pq . zp + eps
//   attn[b,l,h*D+d] = num/den   (written in [B,L,E] layout for final GEMM)
// ---------------------------------------------------------------------------
#define ATTN_SMEM ((3 * C_ * 65 + 2 * C_ * D_ + D_) * 4)

__global__ __launch_bounds__(256)
void attn_kernel()
{
    extern __shared__ float sm[];
    float* pq_s = sm;                 // 64 x 65 (padded)
    float* pk_s = pq_s + C_ * 65;     // 64 x 65
    float* A_s  = pk_s + C_ * 65;     // 64 x 65
    float* v_s  = A_s + C_ * 65;      // 64 x 64
    float* S_s  = v_s + C_ * D_;      // 64 x 64
    float* z_s  = S_s + D_ * D_;      // 64

    int chunk = blockIdx.x, bh = blockIdx.y;
    int tid = threadIdx.x, ty = tid >> 4, tx = tid & 15;
    size_t rb = ((size_t)bh * L_ + (size_t)chunk * C_) * D_;

    for (int idx = tid; idx < C_ * D_; idx += 256) {
        int r = idx >> 6, c = idx & 63;
        pq_s[r * 65 + c] = g_pq[rb + idx];
        pk_s[r * 65 + c] = g_pk[rb + idx];
    }
    const float4* v4 = reinterpret_cast<const float4*>(g_v + rb);
    const float4* S4 = reinterpret_cast<const float4*>(g_Sp + ((size_t)bh * NC_ + chunk) * D_ * D_);
#pragma unroll
    for (int u = 0; u < 4; u++) {
        int f = tid + u * 256;
        reinterpret_cast<float4*>(v_s)[f] = v4[f];
        reinterpret_cast<float4*>(S_s)[f] = S4[f];
    }
    if (tid < 16)
        reinterpret_cast<float4*>(z_s)[tid] =
            reinterpret_cast<const float4*>(g_zp + ((size_t)bh * NC_ + chunk) * D_)[tid];
    __syncthreads();

    // Phase 1: A = pq @ pk^T with inclusive causal mask (r >= c)
    float a[4][4];
#pragma unroll
    for (int i = 0; i < 4; i++)
#pragma unroll
        for (int j = 0; j < 4; j++) a[i][j] = 0.f;
    for (int k = 0; k < D_; k++) {
        float pa[4], pb[4];
#pragma unroll
        for (int i = 0; i < 4; i++) pa[i] = pq_s[(ty * 4 + i) * 65 + k];
#pragma unroll
        for (int j = 0; j < 4; j++) pb[j] = pk_s[(tx * 4 + j) * 65 + k];
#pragma unroll
        for (int i = 0; i < 4; i++)
#pragma unroll
            for (int j = 0; j < 4; j++) a[i][j] += pa[i] * pb[j];
    }
#pragma unroll
    for (int i = 0; i < 4; i++)
#pragma unroll
        for (int j = 0; j < 4; j++)
            if ((ty * 4 + i) < (tx * 4 + j)) a[i][j] = 0.f;
#pragma unroll
    for (int i = 0; i < 4; i++)
#pragma unroll
        for (int j = 0; j < 4; j++)
            A_s[(ty * 4 + i) * 65 + tx * 4 + j] = a[i][j];
    __syncthreads();

    // Phase 2: num = A @ v + pq @ S ; den = rowsum(A) + pq . z
    float num[4][4]; float den[4];
#pragma unroll
    for (int i = 0; i < 4; i++) { den[i] = 0.f;
#pragma unroll
        for (int j = 0; j < 4; j++) num[i][j] = 0.f; }

    for (int k = 0; k < C_; k++) {      // C_ == D_ == 64: shared K loop
        float av[4], pv[4], vv[4], sv[4];
#pragma unroll
        for (int i = 0; i < 4; i++) av[i] = A_s[(ty * 4 + i) * 65 + k];
#pragma unroll
        for (int i = 0; i < 4; i++) pv[i] = pq_s[(ty * 4 + i) * 65 + k];
#pragma unroll
        for (int j = 0; j < 4; j++) vv[j] = v_s[k * D_ + tx * 4 + j];
#pragma unroll
        for (int j = 0; j < 4; j++) sv[j] = S_s[k * D_ + tx * 4 + j];
        float zk = z_s[k];
#pragma unroll
        for (int i = 0; i < 4; i++) {
            den[i] += av[i] + pv[i] * zk;
#pragma unroll
            for (int j = 0; j < 4; j++) num[i][j] += av[i] * vv[j] + pv[i] * sv[j];
        }
    }

    int b = bh >> 4, h = bh & (H_ - 1);
#pragma unroll
    for (int i = 0; i < 4; i++) {
        int l = chunk * C_ + ty * 4 + i;
        float dinv = 1.f / (den[i] + 1e-5f);
        float* op = g_at + ((size_t)b * L_ + l) * E_ + h * D_ + tx * 4;
#pragma unroll
        for (int j = 0; j < 4; j++) op[j] = num[i][j] * dinv;
    }
}

// ---------------------------------------------------------------------------
extern "C" void kernel_launch(void* const* d_in, const int* in_sizes, int n_in,
                              void* d_out, int out_size)
{
    (void)in_sizes; (void)n_in; (void)out_size;
    const float* x  = (const float*)d_in[0];
    const float* Wq = (const float*)d_in[1];
    const float* Wk = (const float*)d_in[2];
    const float* Wv = (const float*)d_in[3];
    const float* Wo = (const float*)d_in[4];
    const float* bo = (const float*)d_in[5];
    float* out = (float*)d_out;

    float *pq, *pk, *v, *at;
    cudaGetSymbolAddress((void**)&pq, g_pq);
    cudaGetSymbolAddress((void**)&pk, g_pk);
    cudaGetSymbolAddress((void**)&v,  g_v);
    cudaGetSymbolAddress((void**)&at, g_at);

    cudaFuncSetAttribute(attn_kernel, cudaFuncAttributeMaxDynamicSharedMemorySize, ATTN_SMEM);

    dim3 gg(E_ / 128, M_ / 128);
    gemm_nt<1><<<gg, 256>>>(x, Wq, nullptr, pq, M_, E_, E_);
    gemm_nt<1><<<gg, 256>>>(x, Wk, nullptr, pk, M_, E_, E_);
    gemm_nt<0><<<gg, 256>>>(x, Wv, nullptr, v,  M_, E_, E_);
    chunk_state_kernel<<<dim3(NC_, BH_), 256>>>();
    prefix_kernel<<<BH_, 256>>>();
    attn_kernel<<<dim3(NC_, BH_), 256, ATTN_SMEM>>>();
    gemm_nt<2><<<gg, 256>>>(at, Wo, bo, out, M_, E_, E_);
}

// round 3
// speedup vs baseline: 2.6814x; 2.6814x over previous
#include <cuda_runtime.h>
#include <math.h>
#include <stdint.h>

#define B_ 4
#define L_ 4096
#define E_ 1024
#define H_ 16
#define D_ 64
#define C_ 64
#define NC_ (L_/C_)     // 64 chunks
#define BH_ (B_*H_)     // 64
#define M_ (B_*L_)      // 16384
#define K_ 1024

// Scratch (device globals; allocation-free per harness rules)
__device__ float g_pq[(size_t)BH_*L_*D_];
__device__ float g_pk[(size_t)BH_*L_*D_];
__device__ float g_v [(size_t)BH_*L_*D_];
__device__ float g_Sl[(size_t)BH_*NC_*D_*D_];
__device__ float g_Sp[(size_t)BH_*NC_*D_*D_];
__device__ float g_zl[(size_t)BH_*NC_*D_];
__device__ float g_zp[(size_t)BH_*NC_*D_];
__device__ float g_at[(size_t)M_*E_];

// ---------------------------------------------------------------------------
// tf32 mma.sync NT GEMM: C[m][n] = sum_k A[m][k] * Bm[n][k]
// Tile 128x128, BK=32, 8 warps (each 32m x 64n), m16n8k8 tf32 fragments.
// smem row stride 36 floats -> conflict-free LDS for fragments and STS.128.
// MODE 0: identity -> [B,H,L,D];  MODE 1: elu+1 -> [B,H,L,D];  MODE 2: +bias -> [M,N]
// ---------------------------------------------------------------------------
#define TKC 32
#define NKC (K_ / TKC)      // 32 chunks
#define PADK 36             // smem row stride in floats

__device__ __forceinline__ uint32_t f2tf32(float x) {
    uint32_t r;
    asm("cvt.rna.tf32.f32 %0, %1;" : "=r"(r) : "f"(x));
    return r;
}

__device__ __forceinline__ void mma_tf32(float c[4], uint32_t a0, uint32_t a1,
                                         uint32_t a2, uint32_t a3,
                                         uint32_t b0, uint32_t b1) {
    asm volatile(
        "mma.sync.aligned.m16n8k8.row.col.f32.tf32.tf32.f32 "
        "{%0,%1,%2,%3}, {%4,%5,%6,%7}, {%8,%9}, {%0,%1,%2,%3};"
        : "+f"(c[0]), "+f"(c[1]), "+f"(c[2]), "+f"(c[3])
        : "r"(a0), "r"(a1), "r"(a2), "r"(a3), "r"(b0), "r"(b1));
}

template<int MODE>
__global__ __launch_bounds__(256)
void mma_gemm(const float* __restrict__ A, const float* __restrict__ Bm,
              const float* __restrict__ bias, float* __restrict__ C)
{
    __shared__ float As[128 * PADK];
    __shared__ float Bs[128 * PADK];

    int tid = threadIdx.x;
    int wid = tid >> 5, lane = tid & 31;
    int m0 = blockIdx.y * 128, n0 = blockIdx.x * 128;

    // loader mapping: thread handles rows row0 + u*32 (u=0..3), fixed kv
    int row0 = tid >> 3;
    int kv = (tid & 7) * 4;

    const float* pA = A + (size_t)(m0 + row0) * K_ + kv;
    const float* pB = Bm + (size_t)(n0 + row0) * K_ + kv;

    int warp_m = (wid >> 1) * 32;
    int warp_n = (wid & 1) * 64;
    int g = lane >> 2, tig = lane & 3;

    float c[2][8][4];
#pragma unroll
    for (int mf = 0; mf < 2; mf++)
#pragma unroll
        for (int nf = 0; nf < 8; nf++)
#pragma unroll
            for (int q = 0; q < 4; q++) c[mf][nf][q] = 0.f;

    float4 ra[4], rb[4];
#pragma unroll
    for (int u = 0; u < 4; u++) {
        ra[u] = *reinterpret_cast<const float4*>(pA + (size_t)u * 32 * K_);
        rb[u] = *reinterpret_cast<const float4*>(pB + (size_t)u * 32 * K_);
    }

    for (int kc = 0; kc < NKC; kc++) {
        __syncthreads();   // previous compute done before overwrite
#pragma unroll
        for (int u = 0; u < 4; u++) {
            int off = (row0 + u * 32) * PADK + kv;
            *reinterpret_cast<uint4*>(&As[off]) =
                make_uint4(f2tf32(ra[u].x), f2tf32(ra[u].y), f2tf32(ra[u].z), f2tf32(ra[u].w));
            *reinterpret_cast<uint4*>(&Bs[off]) =
                make_uint4(f2tf32(rb[u].x), f2tf32(rb[u].y), f2tf32(rb[u].z), f2tf32(rb[u].w));
        }
        __syncthreads();

        if (kc + 1 < NKC) {
            pA += TKC; pB += TKC;
#pragma unroll
            for (int u = 0; u < 4; u++) {
                ra[u] = *reinterpret_cast<const float4*>(pA + (size_t)u * 32 * K_);
                rb[u] = *reinterpret_cast<const float4*>(pB + (size_t)u * 32 * K_);
            }
        }

#pragma unroll
        for (int ks = 0; ks < 4; ks++) {
            int kb = ks * 8 + tig;
            uint32_t a[2][4], b[8][2];
#pragma unroll
            for (int mf = 0; mf < 2; mf++) {
                int m = warp_m + mf * 16 + g;
                a[mf][0] = __float_as_uint(As[m * PADK + kb]);
                a[mf][1] = __float_as_uint(As[(m + 8) * PADK + kb]);
                a[mf][2] = __float_as_uint(As[m * PADK + kb + 4]);
                a[mf][3] = __float_as_uint(As[(m + 8) * PADK + kb + 4]);
            }
#pragma unroll
            for (int nf = 0; nf < 8; nf++) {
                int n = warp_n + nf * 8 + g;
                b[nf][0] = __float_as_uint(Bs[n * PADK + kb]);
                b[nf][1] = __float_as_uint(Bs[n * PADK + kb + 4]);
            }
#pragma unroll
            for (int mf = 0; mf < 2; mf++)
#pragma unroll
                for (int nf = 0; nf < 8; nf++)
                    mma_tf32(c[mf][nf], a[mf][0], a[mf][1], a[mf][2], a[mf][3],
                             b[nf][0], b[nf][1]);
        }
    }

    // Epilogue: c0,c1 at (row, col), (row, col+1); c2,c3 at row+8
#pragma unroll
    for (int mf = 0; mf < 2; mf++) {
#pragma unroll
        for (int half = 0; half < 2; half++) {
            int row = m0 + warp_m + mf * 16 + g + half * 8;
#pragma unroll
            for (int nf = 0; nf < 8; nf++) {
                int col = n0 + warp_n + nf * 8 + 2 * tig;
                float v0 = c[mf][nf][half * 2 + 0];
                float v1 = c[mf][nf][half * 2 + 1];
                if (MODE == 1) {
                    v0 = (v0 > 0.f) ? (v0 + 1.f) : expf(v0);
                    v1 = (v1 > 0.f) ? (v1 + 1.f) : expf(v1);
                }
                if (MODE == 2) {
                    v0 += bias[col]; v1 += bias[col + 1];
                    *reinterpret_cast<float2*>(C + (size_t)row * E_ + col) =
                        make_float2(v0, v1);
                } else {
                    int bb = row >> 12, l = row & (L_ - 1);
                    int h = col >> 6, d = col & (D_ - 1);
                    *reinterpret_cast<float2*>(
                        C + (((size_t)(bb * H_ + h)) * L_ + l) * D_ + d) =
                        make_float2(v0, v1);
                }
            }
        }
    }
}

// ---------------------------------------------------------------------------
// Per-chunk local state: Sl = phi_k^T @ v  (D x D), zl = colsum(phi_k)
// ---------------------------------------------------------------------------
__global__ __launch_bounds__(256)
void chunk_state_kernel()
{
    int chunk = blockIdx.x, bh = blockIdx.y;
    __shared__ float pk_s[C_ * D_];
    __shared__ float v_s [C_ * D_];
    int tid = threadIdx.x;
    size_t rb = ((size_t)bh * L_ + (size_t)chunk * C_) * D_;
    const float4* pk4 = reinterpret_cast<const float4*>(g_pk + rb);
    const float4* v4  = reinterpret_cast<const float4*>(g_v  + rb);
#pragma unroll
    for (int u = 0; u < 4; u++) {
        int f = tid + u * 256;
        reinterpret_cast<float4*>(pk_s)[f] = pk4[f];
        reinterpret_cast<float4*>(v_s)[f]  = v4[f];
    }
    __syncthreads();

    int ty = tid >> 4, tx = tid & 15;
    float s[4][4]; float z[4];
#pragma unroll
    for (int i = 0; i < 4; i++) { z[i] = 0.f;
#pragma unroll
        for (int j = 0; j < 4; j++) s[i][j] = 0.f; }

    for (int r = 0; r < C_; r++) {
        float a[4], b[4];
#pragma unroll
        for (int i = 0; i < 4; i++) a[i] = pk_s[r * D_ + ty * 4 + i];
#pragma unroll
        for (int j = 0; j < 4; j++) b[j] = v_s[r * D_ + tx * 4 + j];
#pragma unroll
        for (int i = 0; i < 4; i++) {
            z[i] += a[i];
#pragma unroll
            for (int j = 0; j < 4; j++) s[i][j] += a[i] * b[j];
        }
    }
    size_t so = ((size_t)bh * NC_ + chunk) * D_ * D_;
#pragma unroll
    for (int i = 0; i < 4; i++)
#pragma unroll
        for (int j = 0; j < 4; j++)
            g_Sl[so + (ty * 4 + i) * D_ + tx * 4 + j] = s[i][j];
    if (tx == 0) {
        size_t zo = ((size_t)bh * NC_ + chunk) * D_;
#pragma unroll
        for (int i = 0; i < 4; i++) g_zl[zo + ty * 4 + i] = z[i];
    }
}

// ---------------------------------------------------------------------------
// Exclusive prefix over chunks (per bh): Sp[c] = sum_{c'<c} Sl[c'], same for z
// ---------------------------------------------------------------------------
__global__ __launch_bounds__(256)
void prefix_kernel()
{
    int bh = blockIdx.x;
    int tid = threadIdx.x;
    float acc[16];
#pragma unroll
    for (int j = 0; j < 16; j++) acc[j] = 0.f;
    for (int c = 0; c < NC_; c++) {
        size_t base = ((size_t)bh * NC_ + c) * D_ * D_;
#pragma unroll
        for (int j = 0; j < 16; j++) {
            int e = tid + j * 256;
            g_Sp[base + e] = acc[j];
            acc[j] += g_Sl[base + e];
        }
    }
    if (tid < D_) {
        float za = 0.f;
        for (int c = 0; c < NC_; c++) {
            size_t zb = ((size_t)bh * NC_ + c) * D_;
            g_zp[zb + tid] = za;
            za += g_zl[zb + tid];
        }
    }
}

// ---------------------------------------------------------------------------
// Fused intra+inter chunk attention.
//   A = tril(pq @ pk^T)  (inclusive)
//   num = A @ v + pq @ Sp;  den = rowsum(A) + pq . zp + eps
//   attn[b,l,h*D+d] = num/den   (written in [B,L,E] layout for final GEMM)
// ---------------------------------------------------------------------------
#define ATTN_SMEM ((3 * C_ * 65 + 2 * C_ * D_ + D_) * 4)

__global__ __launch_bounds__(256)
void attn_kernel()
{
    extern __shared__ float sm[];
    float* pq_s = sm;                 // 64 x 65 (padded)
    float* pk_s = pq_s + C_ * 65;     // 64 x 65
    float* A_s  = pk_s + C_ * 65;     // 64 x 65
    float* v_s  = A_s + C_ * 65;      // 64 x 64
    float* S_s  = v_s + C_ * D_;      // 64 x 64
    float* z_s  = S_s + D_ * D_;      // 64

    int chunk = blockIdx.x, bh = blockIdx.y;
    int tid = threadIdx.x, ty = tid >> 4, tx = tid & 15;
    size_t rb = ((size_t)bh * L_ + (size_t)chunk * C_) * D_;

    for (int idx = tid; idx < C_ * D_; idx += 256) {
        int r = idx >> 6, c = idx & 63;
        pq_s[r * 65 + c] = g_pq[rb + idx];
        pk_s[r * 65 + c] = g_pk[rb + idx];
    }
    const float4* v4 = reinterpret_cast<const float4*>(g_v + rb);
    const float4* S4 = reinterpret_cast<const float4*>(g_Sp + ((size_t)bh * NC_ + chunk) * D_ * D_);
#pragma unroll
    for (int u = 0; u < 4; u++) {
        int f = tid + u * 256;
        reinterpret_cast<float4*>(v_s)[f] = v4[f];
        reinterpret_cast<float4*>(S_s)[f] = S4[f];
    }
    if (tid < 16)
        reinterpret_cast<float4*>(z_s)[tid] =
            reinterpret_cast<const float4*>(g_zp + ((size_t)bh * NC_ + chunk) * D_)[tid];
    __syncthreads();

    // Phase 1: A = pq @ pk^T with inclusive causal mask (r >= c)
    float a[4][4];
#pragma unroll
    for (int i = 0; i < 4; i++)
#pragma unroll
        for (int j = 0; j < 4; j++) a[i][j] = 0.f;
    for (int k = 0; k < D_; k++) {
        float pa[4], pb[4];
#pragma unroll
        for (int i = 0; i < 4; i++) pa[i] = pq_s[(ty * 4 + i) * 65 + k];
#pragma unroll
        for (int j = 0; j < 4; j++) pb[j] = pk_s[(tx * 4 + j) * 65 + k];
#pragma unroll
        for (int i = 0; i < 4; i++)
#pragma unroll
            for (int j = 0; j < 4; j++) a[i][j] += pa[i] * pb[j];
    }
#pragma unroll
    for (int i = 0; i < 4; i++)
#pragma unroll
        for (int j = 0; j < 4; j++)
            if ((ty * 4 + i) < (tx * 4 + j)) a[i][j] = 0.f;
#pragma unroll
    for (int i = 0; i < 4; i++)
#pragma unroll
        for (int j = 0; j < 4; j++)
            A_s[(ty * 4 + i) * 65 + tx * 4 + j] = a[i][j];
    __syncthreads();

    // Phase 2: num = A @ v + pq @ S ; den = rowsum(A) + pq . z
    float num[4][4]; float den[4];
#pragma unroll
    for (int i = 0; i < 4; i++) { den[i] = 0.f;
#pragma unroll
        for (int j = 0; j < 4; j++) num[i][j] = 0.f; }

    for (int k = 0; k < C_; k++) {      // C_ == D_ == 64: shared K loop
        float av[4], pv[4], vv[4], sv[4];
#pragma unroll
        for (int i = 0; i < 4; i++) av[i] = A_s[(ty * 4 + i) * 65 + k];
#pragma unroll
        for (int i = 0; i < 4; i++) pv[i] = pq_s[(ty * 4 + i) * 65 + k];
#pragma unroll
        for (int j = 0; j < 4; j++) vv[j] = v_s[k * D_ + tx * 4 + j];
#pragma unroll
        for (int j = 0; j < 4; j++) sv[j] = S_s[k * D_ + tx * 4 + j];
        float zk = z_s[k];
#pragma unroll
        for (int i = 0; i < 4; i++) {
            den[i] += av[i] + pv[i] * zk;
#pragma unroll
            for (int j = 0; j < 4; j++) num[i][j] += av[i] * vv[j] + pv[i] * sv[j];
        }
    }

    int b = bh >> 4, h = bh & (H_ - 1);
#pragma unroll
    for (int i = 0; i < 4; i++) {
        int l = chunk * C_ + ty * 4 + i;
        float dinv = 1.f / (den[i] + 1e-5f);
        float* op = g_at + ((size_t)b * L_ + l) * E_ + h * D_ + tx * 4;
#pragma unroll
        for (int j = 0; j < 4; j++) op[j] = num[i][j] * dinv;
    }
}

// ---------------------------------------------------------------------------
extern "C" void kernel_launch(void* const* d_in, const int* in_sizes, int n_in,
                              void* d_out, int out_size)
{
    (void)in_sizes; (void)n_in; (void)out_size;
    const float* x  = (const float*)d_in[0];
    const float* Wq = (const float*)d_in[1];
    const float* Wk = (const float*)d_in[2];
    const float* Wv = (const float*)d_in[3];
    const float* Wo = (const float*)d_in[4];
    const float* bo = (const float*)d_in[5];
    float* out = (float*)d_out;

    float *pq, *pk, *v, *at;
    cudaGetSymbolAddress((void**)&pq, g_pq);
    cudaGetSymbolAddress((void**)&pk, g_pk);
    cudaGetSymbolAddress((void**)&v,  g_v);
    cudaGetSymbolAddress((void**)&at, g_at);

    cudaFuncSetAttribute(attn_kernel, cudaFuncAttributeMaxDynamicSharedMemorySize, ATTN_SMEM);

    dim3 gg(E_ / 128, M_ / 128);
    mma_gemm<1><<<gg, 256>>>(x, Wq, nullptr, pq);
    mma_gemm<1><<<gg, 256>>>(x, Wk, nullptr, pk);
    mma_gemm<0><<<gg, 256>>>(x, Wv, nullptr, v);
    chunk_state_kernel<<<dim3(NC_, BH_), 256>>>();
    prefix_kernel<<<BH_, 256>>>();
    attn_kernel<<<dim3(NC_, BH_), 256, ATTN_SMEM>>>();
    mma_gemm<2><<<gg, 256>>>(at, Wo, bo, out);
}